// round 14
// baseline (speedup 1.0000x reference)
#include <cuda_runtime.h>
#include <cstdint>

// SpikeFP32Embedding: out[t, :] = weight_pulse[token_ids[t], :]
// weight_pulse: [32768, 128, 32] fp32  -> 1024 float4 per row (16 KB)
// token_ids:    16384 int32
// out:          [16384, 4096] fp32  (256 MB)
//
// ROOFLINE-FINAL. Traffic is at the analytic floor (268 MB mandatory writes
// + ~197 MB reads = unique-row floor with perfect intra-launch L2 dedup);
// DRAM efficiency is pinned at ~78% by read/write bus turnaround, which no
// kernel-side mechanism (TMA bulk, MLP depth, L2 evict policies, store
// policies) moved. Config = best measured:
//   - reads:  __ldg LDG.128, front-batched 4/thread
//   - stores: default write-back STG.128 (best DRAM%: 78.4)
//   - 8 tokens per CTA (grid 2048): 8x fewer CTA dispatches and dependent
//     token-id startup bubbles; ids staged once through smem.

static constexpr int ROW_F4   = 1024;   // 4096 floats / 4
static constexpr int THREADS  = 256;
static constexpr int F4_PER_T = ROW_F4 / THREADS;  // 4
static constexpr int TOK_PER_CTA = 8;
static constexpr int N_TOKENS = 16384;

__global__ void __launch_bounds__(THREADS)
spike_embed_gather_v8(const int* __restrict__ token_ids,
                      const float4* __restrict__ table,
                      float4* __restrict__ out)
{
    __shared__ int ids[TOK_PER_CTA];

    const int tok0 = blockIdx.x * TOK_PER_CTA;
    const int tid  = threadIdx.x;

    if (tid < TOK_PER_CTA)
        ids[tid] = __ldg(&token_ids[tok0 + tid]);
    __syncthreads();

    float4* __restrict__ dst = out + (size_t)tok0 * ROW_F4;

#pragma unroll
    for (int t = 0; t < TOK_PER_CTA; ++t) {
        const float4* __restrict__ src = table + (size_t)ids[t] * ROW_F4;

        float4 v[F4_PER_T];
#pragma unroll
        for (int i = 0; i < F4_PER_T; ++i)
            v[i] = __ldg(&src[tid + i * THREADS]);
#pragma unroll
        for (int i = 0; i < F4_PER_T; ++i)
            dst[(size_t)t * ROW_F4 + tid + i * THREADS] = v[i];
    }
}

extern "C" void kernel_launch(void* const* d_in, const int* in_sizes, int n_in,
                              void* d_out, int out_size)
{
    // Resolve inputs by element count:
    //   token_ids:    16384
    //   weight_pulse: 134217728
    const int* token_ids = nullptr;
    const float4* table  = nullptr;
    for (int i = 0; i < n_in; ++i) {
        if (in_sizes[i] == 16384)          token_ids = (const int*)d_in[i];
        else if (in_sizes[i] == 134217728) table     = (const float4*)d_in[i];
    }

    spike_embed_gather_v8<<<N_TOKENS / TOK_PER_CTA, THREADS>>>(
        token_ids, table, (float4*)d_out);
}

// round 16
// speedup vs baseline: 1.0259x; 1.0259x over previous
#include <cuda_runtime.h>
#include <cstdint>

// SpikeFP32Embedding: out[t, :] = weight_pulse[token_ids[t], :]
// weight_pulse: [32768, 128, 32] fp32  -> 4096 floats = 1024 float4 per row
// token_ids:    [8, 2048] int32        -> 16384 tokens
// out:          [16384, 4096] fp32
//
// FINAL — proven-best configuration (R2: 80.4us wall, 75.2us kernel,
// DRAM 77.1%). Nine structural/policy variants (2-token CTAs, TMA bulk
// copy pipelines, L2 evict_last pinning x2, write-back vs streaming
// stores, cg vs nc loads, 8-token CTAs) all land in 74.3-76.9us kernel /
// 76.4-78.4% DRAM with traffic invariant at ~460 MB = the analytic floor
// (268 MB mandatory writes + ~195 MB unique-row reads with perfect
// intra-launch L2 dedup). The residual ~22% of DRAM peak is read/write
// bus turnaround on a mandatory mixed stream — not addressable from the
// kernel. One CTA per token; 256 threads x 4 front-batched LDG.128;
// streaming stores keep L2 clean for the gather reads.

static constexpr int ROW_F4   = 1024;   // 4096 floats / 4
static constexpr int THREADS  = 256;
static constexpr int F4_PER_T = ROW_F4 / THREADS;  // 4

__device__ __forceinline__ void stcs_f4(float4* addr, const float4& v) {
    asm volatile("st.global.cs.v4.f32 [%0], {%1, %2, %3, %4};"
                 :: "l"(addr), "f"(v.x), "f"(v.y), "f"(v.z), "f"(v.w)
                 : "memory");
}

__global__ void __launch_bounds__(THREADS)
spike_embed_gather(const int* __restrict__ token_ids,
                   const float4* __restrict__ table,
                   float4* __restrict__ out)
{
    const int tok = blockIdx.x;
    const int row = __ldg(&token_ids[tok]);

    const float4* __restrict__ src = table + (size_t)row * ROW_F4;
    float4* __restrict__       dst = out   + (size_t)tok * ROW_F4;

    const int tid = threadIdx.x;
    float4 v[F4_PER_T];
#pragma unroll
    for (int i = 0; i < F4_PER_T; ++i)
        v[i] = __ldg(&src[tid + i * THREADS]);
#pragma unroll
    for (int i = 0; i < F4_PER_T; ++i)
        stcs_f4(&dst[tid + i * THREADS], v[i]);
}

extern "C" void kernel_launch(void* const* d_in, const int* in_sizes, int n_in,
                              void* d_out, int out_size)
{
    // Resolve input order by element count (robust to metadata ordering):
    //   token_ids:    8*2048            = 16384
    //   weight_pulse: 32768*128*32      = 134217728
    const int* token_ids = nullptr;
    const float4* table  = nullptr;
    for (int i = 0; i < n_in; ++i) {
        if (in_sizes[i] == 16384)          token_ids = (const int*)d_in[i];
        else if (in_sizes[i] == 134217728) table     = (const float4*)d_in[i];
    }

    const int n_tokens = 16384;
    spike_embed_gather<<<n_tokens, THREADS>>>(token_ids, table, (float4*)d_out);
}